// round 1
// baseline (speedup 1.0000x reference)
#include <cuda_runtime.h>

// Problem shape (fixed by setup_inputs): x[B=2, F=12, C=64, H=256, W=256], pad=1, NCHW.
// Output: [2, 12, 64, 258, 258].

#define B_ 2
#define F_ 12
#define C_ 64
#define H_ 256
#define P_ 1

#define HO_ (H_ + 2 * P_)          // 258
#define PLANE_IN (H_ * H_)         // 65536
#define PLANE_OUT (HO_ * HO_)      // 66564
#define NPLANES (B_ * F_ * C_)     // 1536

// Fetch in[nf (same b,c), applied-rotation rot, row i, col j].
// rot: 0 = identity; 1 = rot90 CCW (out[i,j]=in[j,H-1-i]);
//      2 = 180;      3 = rot90 CW  (out[i,j]=in[H-1-j,i]).
__device__ __forceinline__ float hpx_fetch(const float* __restrict__ in,
                                           int plane, int f, int nf, int rot,
                                           int i, int j) {
    int yy, xx;
    switch (rot) {
        case 0: yy = i;           xx = j;           break;
        case 1: yy = j;           xx = H_ - 1 - i;  break;
        case 2: yy = H_ - 1 - i;  xx = H_ - 1 - j;  break;
        default: yy = H_ - 1 - j; xx = i;           break;
    }
    return in[(plane + (nf - f) * C_) * PLANE_IN + yy * H_ + xx];
}

__global__ void __launch_bounds__(256) hpx_pad_kernel(const float* __restrict__ in,
                                                      float* __restrict__ out) {
    const int rem = blockIdx.x * blockDim.x + threadIdx.x;
    if (rem >= PLANE_OUT) return;
    const int plane = blockIdx.y;            // (b*12 + f)*C + c
    const int yo = rem / HO_;
    const int xo = rem - yo * HO_;
    const int y = yo - P_;
    const int x = xo - P_;

    float v;
    if ((unsigned)y < (unsigned)H_ && (unsigned)x < (unsigned)H_) {
        // Hot path: interior copy (98.5% of threads), fully coalesced.
        v = in[plane * PLANE_IN + y * H_ + x];
    } else {
        const int f = (plane >> 6) % F_;     // plane / C_ (C_=64) mod 12
        const int i = f & 3;
        const int cls = f >> 2;              // 0 = north polar, 1 = equatorial, 2 = south polar

        const int ry = (y < 0) ? 0 : (y < H_ ? 1 : 2);
        const int rx = (x < 0) ? 0 : (x < H_ ? 1 : 2);
        const int reg = ry * 3 + rx;         // 0..8, 4 = interior (excluded)
        const int ti = (ry == 0) ? H_ + y : (ry == 1 ? y : y - H_);
        const int tj = (rx == 0) ? H_ + x : (rx == 1 ? x : x - H_);

        int nf = f, rot = 0;
        bool done = false;

        if (cls == 0) {
            // North polar faces 0-3
            switch (reg) {
                case 0: nf = (i + 2) & 3; rot = 2; break;                 // TL
                case 1: nf = (i + 1) & 3; rot = 1; break;                 // T
                case 2: nf = (i + 1) & 3; rot = 3; break;                 // TR
                case 3: nf = (i + 3) & 3;          break;                 // L
                case 5: nf = ((i + 1) & 3) + 4;    break;                 // R
                case 6: nf = (i + 3) & 3;          break;                 // BL
                case 7: nf = i + 4;                break;                 // B
                default: nf = i + 8;               break;                 // BR
            }
        } else if (cls == 1) {
            // Equatorial faces 4-7 (tri-point corners at TL and BR)
            switch (reg) {
                case 0: {  // synthesized TL corner
                    const int ic = ti - (H_ - P_), jc = tj - (H_ - P_);
                    const int nt = i, nl = (i + 3) & 3;
                    if (ic == P_ - 1 && jc == P_ - 1)
                        v = 0.5f * (hpx_fetch(in, plane, f, nt, 0, H_ - 1, 0) +
                                    hpx_fetch(in, plane, f, nl, 0, 0, H_ - 1));
                    else if (jc == P_ - 1) v = hpx_fetch(in, plane, f, nt, 0, ti, 0);
                    else if (ic == P_ - 1) v = hpx_fetch(in, plane, f, nl, 0, 0, tj);
                    else v = 0.0f;
                    done = true;
                    break;
                }
                case 1: nf = i;                 break;                    // T
                case 2: nf = (i + 1) & 3;       break;                    // TR
                case 3: nf = (i + 3) & 3;       break;                    // L
                case 5: nf = ((i + 1) & 3) + 4; break;                    // R
                case 6: nf = ((i + 3) & 3) + 4; break;                    // BL
                case 7: nf = i + 8;             break;                    // B
                default: { // reg 8: synthesized BR corner
                    const int nb = i + 8, nr = ((i + 1) & 3) + 4;
                    if (ti == 0 && tj == 0)
                        v = 0.5f * (hpx_fetch(in, plane, f, nb, 0, 0, H_ - 1) +
                                    hpx_fetch(in, plane, f, nr, 0, H_ - 1, 0));
                    else if (tj == 0) v = hpx_fetch(in, plane, f, nb, 0, ti, H_ - 1);
                    else if (ti == 0) v = hpx_fetch(in, plane, f, nr, 0, H_ - 1, tj);
                    else v = 0.0f;
                    done = true;
                    break;
                }
            }
        } else {
            // South polar faces 8-11
            switch (reg) {
                case 0: nf = i;                           break;          // TL
                case 1: nf = i + 4;                       break;          // T
                case 2: nf = ((i + 1) & 3) + 4;           break;          // TR
                case 3: nf = ((i + 3) & 3) + 4;           break;          // L
                case 5: nf = ((i + 1) & 3) + 8;           break;          // R
                case 6: nf = ((i + 3) & 3) + 8; rot = 3;  break;          // BL
                case 7: nf = ((i + 3) & 3) + 8; rot = 1;  break;          // B
                default: nf = ((i + 3) & 3) + 8; rot = 2; break;          // BR
            }
        }

        if (!done) v = hpx_fetch(in, plane, f, nf, rot, ti, tj);
    }

    out[plane * PLANE_OUT + rem] = v;
}

extern "C" void kernel_launch(void* const* d_in, const int* in_sizes, int n_in,
                              void* d_out, int out_size) {
    const float* x = (const float*)d_in[0];
    float* out = (float*)d_out;
    (void)in_sizes; (void)n_in; (void)out_size;

    dim3 block(256);
    dim3 grid((PLANE_OUT + 255) / 256, NPLANES);   // 261 x 1536
    hpx_pad_kernel<<<grid, block>>>(x, out);
}

// round 2
// speedup vs baseline: 2.4810x; 2.4810x over previous
#include <cuda_runtime.h>

// x[B=2, F=12, C=64, H=256, W=256] fp32 NCHW, pad=1 -> out [2,12,64,258,258]

#define B_ 2
#define F_ 12
#define C_ 64
#define H_ 256
#define P_ 1

#define HO_ (H_ + 2 * P_)          // 258
#define PLANE_IN (H_ * H_)         // 65536
#define PLANE_OUT (HO_ * HO_)      // 66564
#define NPLANES (B_ * F_ * C_)     // 1536
#define VEC4_PER_PLANE (PLANE_OUT / 4)  // 16641 (exact)

__device__ __forceinline__ float hpx_fetch(const float* __restrict__ in,
                                           int plane, int f, int nf, int rot,
                                           int i, int j) {
    int yy, xx;
    switch (rot) {
        case 0: yy = i;           xx = j;           break;
        case 1: yy = j;           xx = H_ - 1 - i;  break;
        case 2: yy = H_ - 1 - i;  xx = H_ - 1 - j;  break;
        default: yy = H_ - 1 - j; xx = i;           break;
    }
    return in[(plane + (nf - f) * C_) * PLANE_IN + yy * H_ + xx];
}

// Value of output element (plane, yo, xo). Handles interior + all halo cases.
__device__ float hpx_value(const float* __restrict__ in, int plane, int yo, int xo) {
    const int y = yo - P_;
    const int x = xo - P_;

    if ((unsigned)y < (unsigned)H_ && (unsigned)x < (unsigned)H_)
        return in[plane * PLANE_IN + y * H_ + x];

    const int f = (plane >> 6) % F_;
    const int i = f & 3;
    const int cls = f >> 2;

    const int ry = (y < 0) ? 0 : (y < H_ ? 1 : 2);
    const int rx = (x < 0) ? 0 : (x < H_ ? 1 : 2);
    const int reg = ry * 3 + rx;
    const int ti = (ry == 0) ? H_ + y : (ry == 1 ? y : y - H_);
    const int tj = (rx == 0) ? H_ + x : (rx == 1 ? x : x - H_);

    int nf = f, rot = 0;

    if (cls == 0) {
        switch (reg) {
            case 0: nf = (i + 2) & 3; rot = 2; break;
            case 1: nf = (i + 1) & 3; rot = 1; break;
            case 2: nf = (i + 1) & 3; rot = 3; break;
            case 3: nf = (i + 3) & 3;          break;
            case 5: nf = ((i + 1) & 3) + 4;    break;
            case 6: nf = (i + 3) & 3;          break;
            case 7: nf = i + 4;                break;
            default: nf = i + 8;               break;
        }
    } else if (cls == 1) {
        switch (reg) {
            case 0: {  // tri-point TL
                const int ic = ti - (H_ - P_), jc = tj - (H_ - P_);
                const int nt = i, nl = (i + 3) & 3;
                if (ic == P_ - 1 && jc == P_ - 1)
                    return 0.5f * (hpx_fetch(in, plane, f, nt, 0, H_ - 1, 0) +
                                   hpx_fetch(in, plane, f, nl, 0, 0, H_ - 1));
                if (jc == P_ - 1) return hpx_fetch(in, plane, f, nt, 0, ti, 0);
                if (ic == P_ - 1) return hpx_fetch(in, plane, f, nl, 0, 0, tj);
                return 0.0f;
            }
            case 1: nf = i;                 break;
            case 2: nf = (i + 1) & 3;       break;
            case 3: nf = (i + 3) & 3;       break;
            case 5: nf = ((i + 1) & 3) + 4; break;
            case 6: nf = ((i + 3) & 3) + 4; break;
            case 7: nf = i + 8;             break;
            default: {  // tri-point BR
                const int nb = i + 8, nr = ((i + 1) & 3) + 4;
                if (ti == 0 && tj == 0)
                    return 0.5f * (hpx_fetch(in, plane, f, nb, 0, 0, H_ - 1) +
                                   hpx_fetch(in, plane, f, nr, 0, H_ - 1, 0));
                if (tj == 0) return hpx_fetch(in, plane, f, nb, 0, ti, H_ - 1);
                if (ti == 0) return hpx_fetch(in, plane, f, nr, 0, H_ - 1, tj);
                return 0.0f;
            }
        }
    } else {
        switch (reg) {
            case 0: nf = i;                           break;
            case 1: nf = i + 4;                       break;
            case 2: nf = ((i + 1) & 3) + 4;           break;
            case 3: nf = ((i + 3) & 3) + 4;           break;
            case 5: nf = ((i + 1) & 3) + 8;           break;
            case 6: nf = ((i + 3) & 3) + 8; rot = 3;  break;
            case 7: nf = ((i + 3) & 3) + 8; rot = 1;  break;
            default: nf = ((i + 3) & 3) + 8; rot = 2; break;
        }
    }
    return hpx_fetch(in, plane, f, nf, rot, ti, tj);
}

__global__ void __launch_bounds__(256) hpx_pad_vec4_kernel(const float* __restrict__ in,
                                                           float* __restrict__ out) {
    const int t = blockIdx.x * blockDim.x + threadIdx.x;
    if (t >= VEC4_PER_PLANE) return;
    const int plane = blockIdx.y;
    const int rem = t * 4;                 // flattened index within output plane
    const int yo = rem / HO_;
    const int xo = rem - yo * HO_;

    float4 v;
    // Fast path: all 4 elements interior, same row (xo..xo+3 within [1,256], yo in [1,256]).
    if (yo >= P_ && yo <= H_ && xo >= P_ && xo + 3 <= H_) {
        const float* s = in + plane * PLANE_IN + (yo - P_) * H_ + (xo - P_);
        v.x = __ldg(s + 0);
        v.y = __ldg(s + 1);
        v.z = __ldg(s + 2);
        v.w = __ldg(s + 3);
    } else {
        int y0 = yo, x0 = xo;
        float r[4];
        #pragma unroll
        for (int k = 0; k < 4; k++) {
            r[k] = hpx_value(in, plane, y0, x0);
            if (++x0 == HO_) { x0 = 0; ++y0; }
        }
        v.x = r[0]; v.y = r[1]; v.z = r[2]; v.w = r[3];
    }

    *reinterpret_cast<float4*>(out + plane * PLANE_OUT + rem) = v;
}

extern "C" void kernel_launch(void* const* d_in, const int* in_sizes, int n_in,
                              void* d_out, int out_size) {
    const float* x = (const float*)d_in[0];
    float* out = (float*)d_out;
    (void)in_sizes; (void)n_in; (void)out_size;

    dim3 block(256);
    dim3 grid((VEC4_PER_PLANE + 255) / 256, NPLANES);   // 66 x 1536
    hpx_pad_vec4_kernel<<<grid, block>>>(x, out);
}

// round 3
// speedup vs baseline: 3.2335x; 1.3033x over previous
#include <cuda_runtime.h>

// x[B=2, F=12, C=64, H=256, W=256] fp32 NCHW, pad=1 -> out [2,12,64,258,258]

#define B_ 2
#define F_ 12
#define C_ 64
#define H_ 256
#define P_ 1

#define HO_ (H_ + 2 * P_)          // 258
#define PLANE_IN (H_ * H_)         // 65536
#define PLANE_OUT (HO_ * HO_)      // 66564
#define NPLANES (B_ * F_ * C_)     // 1536

#define BULK_BLOCKS 64             // 64 blocks * 256 thr * 4 floats = 65536 = PLANE_IN
#define HALO_ELEMS 1028            // 2*258 (top/bottom rows) + 2*256 (side cols)
#define HALO_BLOCKS 5
#define TOTAL_BLOCKS (BULK_BLOCKS + HALO_BLOCKS)

__device__ __forceinline__ float hpx_fetch(const float* __restrict__ in,
                                           int plane, int f, int nf, int rot,
                                           int i, int j) {
    int yy, xx;
    switch (rot) {
        case 0: yy = i;           xx = j;           break;
        case 1: yy = j;           xx = H_ - 1 - i;  break;
        case 2: yy = H_ - 1 - i;  xx = H_ - 1 - j;  break;
        default: yy = H_ - 1 - j; xx = i;           break;
    }
    return in[(plane + (nf - f) * C_) * PLANE_IN + yy * H_ + xx];
}

// Value of halo output element (plane, yo, xo). (yo,xo) guaranteed non-interior.
__device__ float hpx_halo_value(const float* __restrict__ in, int plane, int yo, int xo) {
    const int y = yo - P_;
    const int x = xo - P_;

    const int f = (plane >> 6) % F_;
    const int i = f & 3;
    const int cls = f >> 2;

    const int ry = (y < 0) ? 0 : (y < H_ ? 1 : 2);
    const int rx = (x < 0) ? 0 : (x < H_ ? 1 : 2);
    const int reg = ry * 3 + rx;
    const int ti = (ry == 0) ? H_ + y : (ry == 1 ? y : y - H_);
    const int tj = (rx == 0) ? H_ + x : (rx == 1 ? x : x - H_);

    int nf = f, rot = 0;

    if (cls == 0) {
        switch (reg) {
            case 0: nf = (i + 2) & 3; rot = 2; break;
            case 1: nf = (i + 1) & 3; rot = 1; break;
            case 2: nf = (i + 1) & 3; rot = 3; break;
            case 3: nf = (i + 3) & 3;          break;
            case 5: nf = ((i + 1) & 3) + 4;    break;
            case 6: nf = (i + 3) & 3;          break;
            case 7: nf = i + 4;                break;
            default: nf = i + 8;               break;
        }
    } else if (cls == 1) {
        switch (reg) {
            case 0: {  // tri-point TL
                const int ic = ti - (H_ - P_), jc = tj - (H_ - P_);
                const int nt = i, nl = (i + 3) & 3;
                if (ic == P_ - 1 && jc == P_ - 1)
                    return 0.5f * (hpx_fetch(in, plane, f, nt, 0, H_ - 1, 0) +
                                   hpx_fetch(in, plane, f, nl, 0, 0, H_ - 1));
                if (jc == P_ - 1) return hpx_fetch(in, plane, f, nt, 0, ti, 0);
                if (ic == P_ - 1) return hpx_fetch(in, plane, f, nl, 0, 0, tj);
                return 0.0f;
            }
            case 1: nf = i;                 break;
            case 2: nf = (i + 1) & 3;       break;
            case 3: nf = (i + 3) & 3;       break;
            case 5: nf = ((i + 1) & 3) + 4; break;
            case 6: nf = ((i + 3) & 3) + 4; break;
            case 7: nf = i + 8;             break;
            default: {  // tri-point BR
                const int nb = i + 8, nr = ((i + 1) & 3) + 4;
                if (ti == 0 && tj == 0)
                    return 0.5f * (hpx_fetch(in, plane, f, nb, 0, 0, H_ - 1) +
                                   hpx_fetch(in, plane, f, nr, 0, H_ - 1, 0));
                if (tj == 0) return hpx_fetch(in, plane, f, nb, 0, ti, H_ - 1);
                if (ti == 0) return hpx_fetch(in, plane, f, nr, 0, H_ - 1, tj);
                return 0.0f;
            }
        }
    } else {
        switch (reg) {
            case 0: nf = i;                           break;
            case 1: nf = i + 4;                       break;
            case 2: nf = ((i + 1) & 3) + 4;           break;
            case 3: nf = ((i + 3) & 3) + 4;           break;
            case 5: nf = ((i + 1) & 3) + 8;           break;
            case 6: nf = ((i + 3) & 3) + 8; rot = 3;  break;
            case 7: nf = ((i + 3) & 3) + 8; rot = 1;  break;
            default: nf = ((i + 3) & 3) + 8; rot = 2; break;
        }
    }
    return hpx_fetch(in, plane, f, nf, rot, ti, tj);
}

__global__ void __launch_bounds__(256) hpx_pad_kernel(const float* __restrict__ in,
                                                      float* __restrict__ out) {
    const int plane = blockIdx.y;

    if (blockIdx.x < BULK_BLOCKS) {
        // ── Bulk: interior copy, input-aligned LDG.128, shifted scalar stores ──
        const int idx = (blockIdx.x << 8) + threadIdx.x;        // 0..16383
        const float4 v = *reinterpret_cast<const float4*>(in + plane * PLANE_IN + (idx << 2));
        const int y = idx >> 6;                                  // input row 0..255
        const int xc = (idx & 63) << 2;                          // input col 0,4,..,252
        float* o = out + plane * PLANE_OUT + (y + P_) * HO_ + P_ + xc;
        o[0] = v.x; o[1] = v.y; o[2] = v.z; o[3] = v.w;
    } else {
        // ── Halo: 1028 elements per plane ──
        const int h = ((blockIdx.x - BULK_BLOCKS) << 8) + threadIdx.x;
        if (h >= HALO_ELEMS) return;
        int yo, xo;
        if (h < HO_) {                 // top row
            yo = 0;        xo = h;
        } else if (h < 2 * HO_) {      // bottom row
            yo = HO_ - 1;  xo = h - HO_;
        } else if (h < 2 * HO_ + H_) { // left column (rows 1..256)
            yo = h - 2 * HO_ + 1;          xo = 0;
        } else {                       // right column (rows 1..256)
            yo = h - (2 * HO_ + H_) + 1;   xo = HO_ - 1;
        }
        out[plane * PLANE_OUT + yo * HO_ + xo] = hpx_halo_value(in, plane, yo, xo);
    }
}

extern "C" void kernel_launch(void* const* d_in, const int* in_sizes, int n_in,
                              void* d_out, int out_size) {
    const float* x = (const float*)d_in[0];
    float* out = (float*)d_out;
    (void)in_sizes; (void)n_in; (void)out_size;

    dim3 block(256);
    dim3 grid(TOTAL_BLOCKS, NPLANES);   // 69 x 1536
    hpx_pad_kernel<<<grid, block>>>(x, out);
}